// round 9
// baseline (speedup 1.0000x reference)
#include <cuda_runtime.h>
#include <cstdint>

typedef unsigned long long u64;
typedef unsigned int u32;

__device__ __forceinline__ u64 ffma2(u64 a, u64 b, u64 c) {
    u64 d; asm("fma.rn.f32x2 %0, %1, %2, %3;" : "=l"(d) : "l"(a), "l"(b), "l"(c)); return d;
}
__device__ __forceinline__ u64 pack2(float x, float y) {
    u64 r; asm("mov.b64 %0, {%1, %2};" : "=l"(r) : "f"(x), "f"(y)); return r;
}
__device__ __forceinline__ float2 unpack2(u64 v) {
    float2 r; asm("mov.b64 {%0, %1}, %2;" : "=f"(r.x), "=f"(r.y) : "l"(v)); return r;
}
__device__ __forceinline__ float clip1(float v) { return fminf(fmaxf(v, -1.0f), 1.0f); }
__device__ __forceinline__ u64 shflx64(u64 v, int m) {
    u32 lo = (u32)v, hi = (u32)(v >> 32);
    lo = __shfl_xor_sync(0xffffffffu, lo, m);
    hi = __shfl_xor_sync(0xffffffffu, hi, m);
    return ((u64)hi << 32) | (u64)lo;
}
__device__ __forceinline__ u64 shfl64(u64 v, int src) {
    u32 lo = (u32)v, hi = (u32)(v >> 32);
    lo = __shfl_sync(0xffffffffu, lo, src);
    hi = __shfl_sync(0xffffffffu, hi, src);
    return ((u64)hi << 32) | (u64)lo;
}
// named barrier over one group (3 warps = 96 threads)
__device__ __forceinline__ void group_bar(int id) {
    asm volatile("bar.sync %0, 96;" :: "r"(id) : "memory");
}

constexpr int NTHREADS = 384;        // 12 warps = 4 groups x 3 warps
constexpr int NGROUP   = 4;
constexpr int WPG      = 3;          // warps per group
constexpr int ROWS_G   = 16;         // rows per group (lane pair per row)
constexpr int ROWS_B   = NGROUP * ROWS_G;   // 64 rows per block-iteration
constexpr int INSTRIDE = 386;        // 386 mod 32 = 2 -> conflict-free across 16 rows
constexpr int VSTRIDE  = 38;

constexpr int SW1_N = 27 * 8;
constexpr int SW2_N = 4 * 8;
constexpr int E1T_N = 19 * 16;
constexpr int E2T_N = 8 * 16;
constexpr int E3S_N = 8;
constexpr int W3S_N = 4;
constexpr int WU_N  = SW1_N + SW2_N + E1T_N + E2T_N + E3S_N + W3S_N;
constexpr int IN_N  = NGROUP * ROWS_G * INSTRIDE;   // floats
constexpr int VB_N  = NGROUP * ROWS_G * VSTRIDE;    // floats
constexpr size_t SMEM_BYTES = (size_t)WU_N * 8 + (size_t)(IN_N + VB_N + 48) * 4;

__global__ __launch_bounds__(NTHREADS, 2)
void lila_kernel(const float* __restrict__ inp,
                 const float* __restrict__ W1, const float* __restrict__ b1,
                 const float* __restrict__ W2, const float* __restrict__ b2,
                 const float* __restrict__ W3, const float* __restrict__ b3,
                 const float* __restrict__ E1, const float* __restrict__ c1,
                 const float* __restrict__ E2, const float* __restrict__ c2,
                 const float* __restrict__ E3, const float* __restrict__ c3,
                 float* __restrict__ out, int B)
{
    extern __shared__ __align__(16) char smem_raw[];
    u64*   SW1 = reinterpret_cast<u64*>(smem_raw);
    u64*   SW2 = SW1 + SW1_N;
    u64*   E1T = SW2 + SW2_N;
    u64*   E2T = E1T + E1T_N;
    u64*   E3S = E2T + E2T_N;
    u64*   W3S = E3S + E3S_N;
    float* IN  = reinterpret_cast<float*>(W3S + W3S_N);
    float* VB  = IN + IN_N;
    float* c1S = VB + VB_N;       // 16
    float* c2S = c1S + 16;        // 16
    float* B1S = c2S + 16;        // 8
    float* B2S = B1S + 8;         // 8

    const int tid  = threadIdx.x;
    const int lane = tid & 31;
    const int warp = tid >> 5;
    const int g    = warp / WPG;         // group 0..3
    const int wsg  = warp - g * WPG;     // warp within group 0..2
    const int r    = lane >> 1;          // row within group (0..15)
    const int h    = lane & 1;           // output half

    // ---- stage weights / constants ----
    for (int i = tid; i < SW1_N; i += NTHREADS) {
        int fp = i >> 3, o = i & 7;
        SW1[i] = pack2(W1[(2 * fp) * 8 + o], W1[(2 * fp + 1) * 8 + o]);
    }
    for (int i = tid; i < SW2_N; i += NTHREADS) {
        int fp = i >> 3, o = i & 7;
        SW2[i] = pack2(W2[(2 * fp) * 8 + o], W2[(2 * fp + 1) * 8 + o]);
    }
    for (int i = tid; i < E1T_N; i += NTHREADS) {
        int fp = i >> 4, o = i & 15;
        E1T[i] = (fp < 18) ? pack2(E1[(2 * fp) * 16 + o], E1[(2 * fp + 1) * 16 + o])
                           : pack2(E1[36 * 16 + o], 0.0f);
    }
    for (int i = tid; i < E2T_N; i += NTHREADS) {
        int fp = i >> 4, o = i & 15;
        E2T[i] = pack2(E2[(2 * fp) * 16 + o], E2[(2 * fp + 1) * 16 + o]);
    }
    if (tid < 8)  E3S[tid] = pack2(E3[2 * tid], E3[2 * tid + 1]);
    if (tid < 4)  W3S[tid] = pack2(W3[2 * tid], W3[2 * tid + 1]);
    if (tid < 16) { c1S[tid] = c1[tid]; c2S[tid] = c2[tid]; }
    if (tid < 8)  { B1S[tid] = b1[tid]; B2S[tid] = b2[tid]; }

    const float b3s = __ldg(b3);
    const float c3s = __ldg(c3);

    const ulonglong2* SW1v = reinterpret_cast<const ulonglong2*>(SW1);
    const ulonglong2* SW2v = reinterpret_cast<const ulonglong2*>(SW2);
    const ulonglong2* E1Tv = reinterpret_cast<const ulonglong2*>(E1T);
    const ulonglong2* E2Tv = reinterpret_cast<const ulonglong2*>(E2T);

    float* grp_in = IN + g * (ROWS_G * INSTRIDE);
    float* grp_vb = VB + g * (ROWS_G * VSTRIDE);
    float* lane_in = grp_in + r * INSTRIDE;
    float* lane_vb = grp_vb + r * VSTRIDE;

    // head mapping (warps 0,1 of each group; warp 2 idles in head phase)
    const int hr  = lane & 7;      // row (within warp's 8)
    const int hoq = lane >> 3;     // output quad
    const float* vrow = grp_vb + (wsg * 8 + hr) * VSTRIDE;

    const int rowsPerIter = gridDim.x * ROWS_B;
    const int barid = g + 1;

    __syncthreads();   // weights staged (block-wide, once)

    for (int rb0 = blockIdx.x * ROWS_B; rb0 < B; rb0 += rowsPerIter) {
        const int rbg = rb0 + g * ROWS_G;        // group's first row

        group_bar(barid);    // protect buffers vs previous iteration readers

        // ---- stage: 3 warps stage 16 rows (stride-3) ----
#pragma unroll 2
        for (int rloc = wsg; rloc < ROWS_G; rloc += WPG) {
            const int row = rbg + rloc;
            float* dst = grp_in + rloc * INSTRIDE;
            if (row < B) {
                const float* src = inp + (size_t)row * 385;
#pragma unroll
                for (int k = 0; k < 12; k++)
                    dst[lane + 32 * k] = __ldg(src + lane + 32 * k);
                if (lane == 0) {
                    grp_vb[rloc * VSTRIDE + 36] = __ldg(src + 384);
                    grp_vb[rloc * VSTRIDE + 37] = 0.0f;
                }
            } else {
#pragma unroll
                for (int k = 0; k < 12; k++)
                    dst[lane + 32 * k] = 0.0f;
                if (lane == 0) {
                    grp_vb[rloc * VSTRIDE + 36] = 0.0f;
                    grp_vb[rloc * VSTRIDE + 37] = 0.0f;
                }
            }
        }
        group_bar(barid);

        // ---- compute: warp owns x-rows {2*wsg, 2*wsg+1}; y-chunks of 3 ----
#pragma unroll 1
        for (int xi = 0; xi < 2; xi++) {
            const int x = 2 * wsg + xi;
            const float* base = lane_in + x * 48;

#pragma unroll 1
            for (int yc = 0; yc < 6; yc += 3) {
                u64 acc[3][4];
#pragma unroll
                for (int j = 0; j < 3; j++)
#pragma unroll
                    for (int q = 0; q < 4; q++) acc[j][q] = 0ull;

                // layer 1: 27 feature-pairs x 3 patches
#pragma unroll 1
                for (int ox = 0; ox < 3; ox++) {
                    const float* brow = base + ox * 48 + yc * 6;
#pragma unroll
                    for (int oy = 0; oy < 3; oy++) {
#pragma unroll
                        for (int j3 = 0; j3 < 3; j3++) {
                            const int fp = 9 * ox + 3 * oy + j3;
                            const int coff = oy * 6 + 2 * j3;
                            const ulonglong2 wa = SW1v[fp * 4 + 2 * h];
                            const ulonglong2 wb = SW1v[fp * 4 + 2 * h + 1];
#pragma unroll
                            for (int j = 0; j < 3; j++) {
                                const u64 iv = *reinterpret_cast<const u64*>(brow + j * 6 + coff);
                                acc[j][0] = ffma2(iv, wa.x, acc[j][0]);
                                acc[j][1] = ffma2(iv, wa.y, acc[j][1]);
                                acc[j][2] = ffma2(iv, wb.x, acc[j][2]);
                                acc[j][3] = ffma2(iv, wb.y, acc[j][3]);
                            }
                        }
                    }
                }

                // epilogue + L2 + L3 per patch
                const float b10 = B1S[4 * h], b11 = B1S[4 * h + 1];
                const float b12 = B1S[4 * h + 2], b13 = B1S[4 * h + 3];
                const float b20 = B2S[4 * h], b21 = B2S[4 * h + 1];
                const float b22 = B2S[4 * h + 2], b23 = B2S[4 * h + 3];
                const u64 w3p0 = W3S[2 * h], w3p1 = W3S[2 * h + 1];

#pragma unroll
                for (int j = 0; j < 3; j++) {
                    float2 f0 = unpack2(acc[j][0]);
                    float2 f1 = unpack2(acc[j][1]);
                    float2 f2 = unpack2(acc[j][2]);
                    float2 f3 = unpack2(acc[j][3]);
                    u64 m0 = pack2(clip1(f0.x + f0.y + b10), clip1(f1.x + f1.y + b11));
                    u64 m1 = pack2(clip1(f2.x + f2.y + b12), clip1(f3.x + f3.y + b13));
                    u64 p0 = shflx64(m0, 1);
                    u64 p1 = shflx64(m1, 1);
                    u64 x0 = h ? p0 : m0, x1 = h ? p1 : m1;
                    u64 x2 = h ? m0 : p0, x3 = h ? m1 : p1;

                    u64 a0 = 0ull, a1 = 0ull, a2 = 0ull, a3 = 0ull;
#pragma unroll
                    for (int fp = 0; fp < 4; fp++) {
                        const u64 xv = (fp == 0) ? x0 : (fp == 1) ? x1 : (fp == 2) ? x2 : x3;
                        const ulonglong2 wa2 = SW2v[fp * 4 + 2 * h];
                        const ulonglong2 wb2 = SW2v[fp * 4 + 2 * h + 1];
                        a0 = ffma2(xv, wa2.x, a0);
                        a1 = ffma2(xv, wa2.y, a1);
                        a2 = ffma2(xv, wb2.x, a2);
                        a3 = ffma2(xv, wb2.y, a3);
                    }
                    float2 g0 = unpack2(a0), g1 = unpack2(a1);
                    float2 g2 = unpack2(a2), g3 = unpack2(a3);
                    u64 n0 = pack2(clip1(g0.x + g0.y + b20), clip1(g1.x + g1.y + b21));
                    u64 n1 = pack2(clip1(g2.x + g2.y + b22), clip1(g3.x + g3.y + b23));

                    u64 s = ffma2(n0, w3p0, ffma2(n1, w3p1, 0ull));
                    float2 sf = unpack2(s);
                    float part = sf.x + sf.y;
                    float tot = part + __shfl_xor_sync(0xffffffffu, part, 1);
                    if (h == 0) lane_vb[x * 6 + yc + j] = clip1(tot + b3s);
                }
            }
        }
        group_bar(barid);

        // ---- head: warps 0,1 handle 8 rows each; warp 2 idle ----
        if (wsg < 2) {
            u64 gacc[4] = {0ull, 0ull, 0ull, 0ull};
#pragma unroll
            for (int fp = 0; fp < 19; fp++) {
                const u64 iv = *reinterpret_cast<const u64*>(vrow + 2 * fp);
                const ulonglong2 wa = E1Tv[fp * 8 + 2 * hoq];
                const ulonglong2 wb = E1Tv[fp * 8 + 2 * hoq + 1];
                gacc[0] = ffma2(iv, wa.x, gacc[0]);
                gacc[1] = ffma2(iv, wa.y, gacc[1]);
                gacc[2] = ffma2(iv, wb.x, gacc[2]);
                gacc[3] = ffma2(iv, wb.y, gacc[3]);
            }
            float gv[4];
#pragma unroll
            for (int k = 0; k < 4; k++) {
                float2 f = unpack2(gacc[k]);
                gv[k] = clip1(f.x + f.y + c1S[4 * hoq + k]);
            }
            u64 q0 = pack2(gv[0], gv[1]), q1 = pack2(gv[2], gv[3]);

            u64 z[8];
#pragma unroll
            for (int c = 0; c < 4; c++) {
                z[2 * c]     = shfl64(q0, c * 8 + hr);
                z[2 * c + 1] = shfl64(q1, c * 8 + hr);
            }

            u64 d[4] = {0ull, 0ull, 0ull, 0ull};
#pragma unroll
            for (int fp = 0; fp < 8; fp++) {
                const ulonglong2 wa = E2Tv[fp * 8 + 2 * hoq];
                const ulonglong2 wb = E2Tv[fp * 8 + 2 * hoq + 1];
                d[0] = ffma2(z[fp], wa.x, d[0]);
                d[1] = ffma2(z[fp], wa.y, d[1]);
                d[2] = ffma2(z[fp], wb.x, d[2]);
                d[3] = ffma2(z[fp], wb.y, d[3]);
            }
            float dv[4];
#pragma unroll
            for (int k = 0; k < 4; k++) {
                float2 f = unpack2(d[k]);
                dv[k] = clip1(f.x + f.y + c2S[4 * hoq + k]);
            }
            u64 s = ffma2(pack2(dv[0], dv[1]), E3S[2 * hoq],
                    ffma2(pack2(dv[2], dv[3]), E3S[2 * hoq + 1], 0ull));
            float2 sf = unpack2(s);
            float part = sf.x + sf.y;
            part += __shfl_xor_sync(0xffffffffu, part, 8);
            part += __shfl_xor_sync(0xffffffffu, part, 16);
            const int row = rbg + wsg * 8 + hr;
            if (hoq == 0 && row < B) out[row] = clip1(part + c3s);
        }
    }
}

extern "C" void kernel_launch(void* const* d_in, const int* in_sizes, int n_in,
                              void* d_out, int out_size)
{
    const float* inp = (const float*)d_in[0];
    const float* W1  = (const float*)d_in[1];
    const float* b1  = (const float*)d_in[2];
    const float* W2  = (const float*)d_in[3];
    const float* b2  = (const float*)d_in[4];
    const float* W3  = (const float*)d_in[5];
    const float* b3  = (const float*)d_in[6];
    const float* E1  = (const float*)d_in[7];
    const float* c1  = (const float*)d_in[8];
    const float* E2  = (const float*)d_in[9];
    const float* c2  = (const float*)d_in[10];
    const float* E3  = (const float*)d_in[11];
    const float* c3  = (const float*)d_in[12];

    int B = in_sizes[0] / 385;

    cudaFuncSetAttribute(lila_kernel, cudaFuncAttributeMaxDynamicSharedMemorySize,
                         (int)SMEM_BYTES);

    lila_kernel<<<296, NTHREADS, SMEM_BYTES>>>(inp, W1, b1, W2, b2, W3, b3,
                                               E1, c1, E2, c2, E3, c3,
                                               (float*)d_out, B);
}

// round 10
// speedup vs baseline: 1.0119x; 1.0119x over previous
#include <cuda_runtime.h>
#include <cstdint>

typedef unsigned long long u64;
typedef unsigned int u32;

__device__ __forceinline__ u64 ffma2(u64 a, u64 b, u64 c) {
    u64 d; asm("fma.rn.f32x2 %0, %1, %2, %3;" : "=l"(d) : "l"(a), "l"(b), "l"(c)); return d;
}
__device__ __forceinline__ u64 pack2(float x, float y) {
    u64 r; asm("mov.b64 %0, {%1, %2};" : "=l"(r) : "f"(x), "f"(y)); return r;
}
__device__ __forceinline__ float2 unpack2(u64 v) {
    float2 r; asm("mov.b64 {%0, %1}, %2;" : "=f"(r.x), "=f"(r.y) : "l"(v)); return r;
}
__device__ __forceinline__ float clip1(float v) { return fminf(fmaxf(v, -1.0f), 1.0f); }
__device__ __forceinline__ u64 shflx64(u64 v, int m) {
    u32 lo = (u32)v, hi = (u32)(v >> 32);
    lo = __shfl_xor_sync(0xffffffffu, lo, m);
    hi = __shfl_xor_sync(0xffffffffu, hi, m);
    return ((u64)hi << 32) | (u64)lo;
}
__device__ __forceinline__ u64 shfl64(u64 v, int src) {
    u32 lo = (u32)v, hi = (u32)(v >> 32);
    lo = __shfl_sync(0xffffffffu, lo, src);
    hi = __shfl_sync(0xffffffffu, hi, src);
    return ((u64)hi << 32) | (u64)lo;
}
// named barrier over one group (4 warps = 128 threads)
__device__ __forceinline__ void group_bar(int id) {
    asm volatile("bar.sync %0, 128;" :: "r"(id) : "memory");
}

constexpr int NTHREADS = 512;        // 16 warps = 4 groups x 4 warps
constexpr int NGROUP   = 4;
constexpr int WPG      = 4;          // warps per group
constexpr int ROWS_G   = 16;         // rows per group (lane pair per row)
constexpr int ROWS_B   = NGROUP * ROWS_G;   // 64 rows per block-iteration
constexpr int RPW      = 4;          // rows staged per warp
constexpr int INSTRIDE = 386;        // 386 mod 32 = 2 -> conflict-free across 16 rows
constexpr int VSTRIDE  = 38;

constexpr int SW1_N = 27 * 8;
constexpr int SW2_N = 4 * 8;
constexpr int E1T_N = 19 * 16;
constexpr int E2T_N = 8 * 16;
constexpr int E3S_N = 8;
constexpr int W3S_N = 4;
constexpr int WU_N  = SW1_N + SW2_N + E1T_N + E2T_N + E3S_N + W3S_N;
constexpr int IN_N  = NGROUP * ROWS_G * INSTRIDE;   // floats
constexpr int VB_N  = NGROUP * ROWS_G * VSTRIDE;    // floats
constexpr size_t SMEM_BYTES = (size_t)WU_N * 8 + (size_t)(IN_N + VB_N + 48) * 4;

__global__ __launch_bounds__(NTHREADS, 1)
void lila_kernel(const float* __restrict__ inp,
                 const float* __restrict__ W1, const float* __restrict__ b1,
                 const float* __restrict__ W2, const float* __restrict__ b2,
                 const float* __restrict__ W3, const float* __restrict__ b3,
                 const float* __restrict__ E1, const float* __restrict__ c1,
                 const float* __restrict__ E2, const float* __restrict__ c2,
                 const float* __restrict__ E3, const float* __restrict__ c3,
                 float* __restrict__ out, int B)
{
    extern __shared__ __align__(16) char smem_raw[];
    u64*   SW1 = reinterpret_cast<u64*>(smem_raw);
    u64*   SW2 = SW1 + SW1_N;
    u64*   E1T = SW2 + SW2_N;
    u64*   E2T = E1T + E1T_N;
    u64*   E3S = E2T + E2T_N;
    u64*   W3S = E3S + E3S_N;
    float* IN  = reinterpret_cast<float*>(W3S + W3S_N);
    float* VB  = IN + IN_N;
    float* c1S = VB + VB_N;       // 16
    float* c2S = c1S + 16;        // 16
    float* B1S = c2S + 16;        // 8
    float* B2S = B1S + 8;         // 8

    const int tid  = threadIdx.x;
    const int lane = tid & 31;
    const int warp = tid >> 5;
    const int g    = warp >> 2;          // group 0..3
    const int wsg  = warp & 3;           // warp within group 0..3
    const int r    = lane >> 1;          // row within group (0..15)
    const int h    = lane & 1;           // output half

    // ---- stage weights / constants ----
    for (int i = tid; i < SW1_N; i += NTHREADS) {
        int fp = i >> 3, o = i & 7;
        SW1[i] = pack2(W1[(2 * fp) * 8 + o], W1[(2 * fp + 1) * 8 + o]);
    }
    for (int i = tid; i < SW2_N; i += NTHREADS) {
        int fp = i >> 3, o = i & 7;
        SW2[i] = pack2(W2[(2 * fp) * 8 + o], W2[(2 * fp + 1) * 8 + o]);
    }
    for (int i = tid; i < E1T_N; i += NTHREADS) {
        int fp = i >> 4, o = i & 15;
        E1T[i] = (fp < 18) ? pack2(E1[(2 * fp) * 16 + o], E1[(2 * fp + 1) * 16 + o])
                           : pack2(E1[36 * 16 + o], 0.0f);
    }
    for (int i = tid; i < E2T_N; i += NTHREADS) {
        int fp = i >> 4, o = i & 15;
        E2T[i] = pack2(E2[(2 * fp) * 16 + o], E2[(2 * fp + 1) * 16 + o]);
    }
    if (tid < 8)  E3S[tid] = pack2(E3[2 * tid], E3[2 * tid + 1]);
    if (tid < 4)  W3S[tid] = pack2(W3[2 * tid], W3[2 * tid + 1]);
    if (tid < 16) { c1S[tid] = c1[tid]; c2S[tid] = c2[tid]; }
    if (tid < 8)  { B1S[tid] = b1[tid]; B2S[tid] = b2[tid]; }

    const float b3s = __ldg(b3);
    const float c3s = __ldg(c3);

    const ulonglong2* SW1v = reinterpret_cast<const ulonglong2*>(SW1);
    const ulonglong2* SW2v = reinterpret_cast<const ulonglong2*>(SW2);
    const ulonglong2* E1Tv = reinterpret_cast<const ulonglong2*>(E1T);
    const ulonglong2* E2Tv = reinterpret_cast<const ulonglong2*>(E2T);

    float* grp_in = IN + g * (ROWS_G * INSTRIDE);
    float* grp_vb = VB + g * (ROWS_G * VSTRIDE);
    float* lane_in = grp_in + r * INSTRIDE;
    float* lane_vb = grp_vb + r * VSTRIDE;

    // head mapping (warps 0,1 of each group handle 8 rows each)
    const int hr  = lane & 7;
    const int hoq = lane >> 3;
    const float* vrow = grp_vb + (wsg * 8 + hr) * VSTRIDE;

    const int rowsPerIter = gridDim.x * ROWS_B;
    const int barid = g + 1;
    const int rbg0 = blockIdx.x * ROWS_B + g * ROWS_G;

    __syncthreads();   // weights staged (block-wide, once)

    // ---- prologue: prefetch first iteration's rows into registers ----
    float pf[RPW][12];
    float cv[RPW];
#pragma unroll
    for (int k = 0; k < RPW; k++) {
        const int row = rbg0 + wsg * RPW + k;
        if (row < B) {
            const float* src = inp + (size_t)row * 385;
#pragma unroll
            for (int j = 0; j < 12; j++)
                pf[k][j] = __ldg(src + lane + 32 * j);
            cv[k] = (lane == 0) ? __ldg(src + 384) : 0.0f;
        } else {
#pragma unroll
            for (int j = 0; j < 12; j++) pf[k][j] = 0.0f;
            cv[k] = 0.0f;
        }
    }

    for (int rbg = rbg0; rbg < B; rbg += rowsPerIter) {

        group_bar(barid);    // protect IN vs prev compute readers, VB vs head readers

        // ---- STS: registers -> SMEM (conflict-free) ----
#pragma unroll
        for (int k = 0; k < RPW; k++) {
            const int rloc = wsg * RPW + k;
            float* dst = grp_in + rloc * INSTRIDE;
#pragma unroll
            for (int j = 0; j < 12; j++)
                dst[lane + 32 * j] = pf[k][j];
            if (lane == 0) {
                grp_vb[rloc * VSTRIDE + 36] = cv[k];
                grp_vb[rloc * VSTRIDE + 37] = 0.0f;
            }
        }
        group_bar(barid);

        // ---- prefetch NEXT iteration (overlaps the compute below) ----
        const int rbgN = rbg + rowsPerIter;
        if (rbgN < B) {
#pragma unroll
            for (int k = 0; k < RPW; k++) {
                const int row = rbgN + wsg * RPW + k;
                if (row < B) {
                    const float* src = inp + (size_t)row * 385;
#pragma unroll
                    for (int j = 0; j < 12; j++)
                        pf[k][j] = __ldg(src + lane + 32 * j);
                    cv[k] = (lane == 0) ? __ldg(src + 384) : 0.0f;
                } else {
#pragma unroll
                    for (int j = 0; j < 12; j++) pf[k][j] = 0.0f;
                    cv[k] = 0.0f;
                }
            }
        }

        // ---- compute: 12 chunks (x 0..5, yc 0/3) per group, 3 per warp ----
#pragma unroll 1
        for (int t = 0; t < 3; t++) {
            const int c   = 3 * wsg + t;     // 0..11
            const int x   = c >> 1;
            const int yc  = (c & 1) * 3;
            const float* base = lane_in + x * 48;

            u64 acc[3][4];
#pragma unroll
            for (int j = 0; j < 3; j++)
#pragma unroll
                for (int q = 0; q < 4; q++) acc[j][q] = 0ull;

            // layer 1: 27 feature-pairs x 3 patches
#pragma unroll 1
            for (int ox = 0; ox < 3; ox++) {
                const float* brow = base + ox * 48 + yc * 6;
#pragma unroll
                for (int oy = 0; oy < 3; oy++) {
#pragma unroll
                    for (int j3 = 0; j3 < 3; j3++) {
                        const int fp = 9 * ox + 3 * oy + j3;
                        const int coff = oy * 6 + 2 * j3;
                        const ulonglong2 wa = SW1v[fp * 4 + 2 * h];
                        const ulonglong2 wb = SW1v[fp * 4 + 2 * h + 1];
#pragma unroll
                        for (int j = 0; j < 3; j++) {
                            const u64 iv = *reinterpret_cast<const u64*>(brow + j * 6 + coff);
                            acc[j][0] = ffma2(iv, wa.x, acc[j][0]);
                            acc[j][1] = ffma2(iv, wa.y, acc[j][1]);
                            acc[j][2] = ffma2(iv, wb.x, acc[j][2]);
                            acc[j][3] = ffma2(iv, wb.y, acc[j][3]);
                        }
                    }
                }
            }

            // epilogue + L2 + L3 per patch
            const float b10 = B1S[4 * h], b11 = B1S[4 * h + 1];
            const float b12 = B1S[4 * h + 2], b13 = B1S[4 * h + 3];
            const float b20 = B2S[4 * h], b21 = B2S[4 * h + 1];
            const float b22 = B2S[4 * h + 2], b23 = B2S[4 * h + 3];
            const u64 w3p0 = W3S[2 * h], w3p1 = W3S[2 * h + 1];

#pragma unroll
            for (int j = 0; j < 3; j++) {
                float2 f0 = unpack2(acc[j][0]);
                float2 f1 = unpack2(acc[j][1]);
                float2 f2 = unpack2(acc[j][2]);
                float2 f3 = unpack2(acc[j][3]);
                u64 m0 = pack2(clip1(f0.x + f0.y + b10), clip1(f1.x + f1.y + b11));
                u64 m1 = pack2(clip1(f2.x + f2.y + b12), clip1(f3.x + f3.y + b13));
                u64 p0 = shflx64(m0, 1);
                u64 p1 = shflx64(m1, 1);
                u64 x0 = h ? p0 : m0, x1 = h ? p1 : m1;
                u64 x2 = h ? m0 : p0, x3 = h ? m1 : p1;

                u64 a0 = 0ull, a1 = 0ull, a2 = 0ull, a3 = 0ull;
#pragma unroll
                for (int fp = 0; fp < 4; fp++) {
                    const u64 xv = (fp == 0) ? x0 : (fp == 1) ? x1 : (fp == 2) ? x2 : x3;
                    const ulonglong2 wa2 = SW2v[fp * 4 + 2 * h];
                    const ulonglong2 wb2 = SW2v[fp * 4 + 2 * h + 1];
                    a0 = ffma2(xv, wa2.x, a0);
                    a1 = ffma2(xv, wa2.y, a1);
                    a2 = ffma2(xv, wb2.x, a2);
                    a3 = ffma2(xv, wb2.y, a3);
                }
                float2 g0 = unpack2(a0), g1 = unpack2(a1);
                float2 g2 = unpack2(a2), g3 = unpack2(a3);
                u64 n0 = pack2(clip1(g0.x + g0.y + b20), clip1(g1.x + g1.y + b21));
                u64 n1 = pack2(clip1(g2.x + g2.y + b22), clip1(g3.x + g3.y + b23));

                u64 s = ffma2(n0, w3p0, ffma2(n1, w3p1, 0ull));
                float2 sf = unpack2(s);
                float part = sf.x + sf.y;
                float tot = part + __shfl_xor_sync(0xffffffffu, part, 1);
                if (h == 0) lane_vb[x * 6 + yc + j] = clip1(tot + b3s);
            }
        }
        group_bar(barid);

        // ---- head: warps 0,1 handle 8 rows each; warps 2,3 idle ----
        if (wsg < 2) {
            u64 gacc[4] = {0ull, 0ull, 0ull, 0ull};
#pragma unroll
            for (int fp = 0; fp < 19; fp++) {
                const u64 iv = *reinterpret_cast<const u64*>(vrow + 2 * fp);
                const ulonglong2 wa = E1Tv[fp * 8 + 2 * hoq];
                const ulonglong2 wb = E1Tv[fp * 8 + 2 * hoq + 1];
                gacc[0] = ffma2(iv, wa.x, gacc[0]);
                gacc[1] = ffma2(iv, wa.y, gacc[1]);
                gacc[2] = ffma2(iv, wb.x, gacc[2]);
                gacc[3] = ffma2(iv, wb.y, gacc[3]);
            }
            float gv[4];
#pragma unroll
            for (int k = 0; k < 4; k++) {
                float2 f = unpack2(gacc[k]);
                gv[k] = clip1(f.x + f.y + c1S[4 * hoq + k]);
            }
            u64 q0 = pack2(gv[0], gv[1]), q1 = pack2(gv[2], gv[3]);

            u64 z[8];
#pragma unroll
            for (int cc = 0; cc < 4; cc++) {
                z[2 * cc]     = shfl64(q0, cc * 8 + hr);
                z[2 * cc + 1] = shfl64(q1, cc * 8 + hr);
            }

            u64 d[4] = {0ull, 0ull, 0ull, 0ull};
#pragma unroll
            for (int fp = 0; fp < 8; fp++) {
                const ulonglong2 wa = E2Tv[fp * 8 + 2 * hoq];
                const ulonglong2 wb = E2Tv[fp * 8 + 2 * hoq + 1];
                d[0] = ffma2(z[fp], wa.x, d[0]);
                d[1] = ffma2(z[fp], wa.y, d[1]);
                d[2] = ffma2(z[fp], wb.x, d[2]);
                d[3] = ffma2(z[fp], wb.y, d[3]);
            }
            float dv[4];
#pragma unroll
            for (int k = 0; k < 4; k++) {
                float2 f = unpack2(d[k]);
                dv[k] = clip1(f.x + f.y + c2S[4 * hoq + k]);
            }
            u64 s = ffma2(pack2(dv[0], dv[1]), E3S[2 * hoq],
                    ffma2(pack2(dv[2], dv[3]), E3S[2 * hoq + 1], 0ull));
            float2 sf = unpack2(s);
            float part = sf.x + sf.y;
            part += __shfl_xor_sync(0xffffffffu, part, 8);
            part += __shfl_xor_sync(0xffffffffu, part, 16);
            const int row = rbg + wsg * 8 + hr;
            if (hoq == 0 && row < B) out[row] = clip1(part + c3s);
        }
    }
}

extern "C" void kernel_launch(void* const* d_in, const int* in_sizes, int n_in,
                              void* d_out, int out_size)
{
    const float* inp = (const float*)d_in[0];
    const float* W1  = (const float*)d_in[1];
    const float* b1  = (const float*)d_in[2];
    const float* W2  = (const float*)d_in[3];
    const float* b2  = (const float*)d_in[4];
    const float* W3  = (const float*)d_in[5];
    const float* b3  = (const float*)d_in[6];
    const float* E1  = (const float*)d_in[7];
    const float* c1  = (const float*)d_in[8];
    const float* E2  = (const float*)d_in[9];
    const float* c2  = (const float*)d_in[10];
    const float* E3  = (const float*)d_in[11];
    const float* c3  = (const float*)d_in[12];

    int B = in_sizes[0] / 385;

    cudaFuncSetAttribute(lila_kernel, cudaFuncAttributeMaxDynamicSharedMemorySize,
                         (int)SMEM_BYTES);

    lila_kernel<<<148, NTHREADS, SMEM_BYTES>>>(inp, W1, b1, W2, b2, W3, b3,
                                               E1, c1, E2, c2, E3, c3,
                                               (float*)d_out, B);
}

// round 11
// speedup vs baseline: 1.0191x; 1.0071x over previous
#include <cuda_runtime.h>
#include <cstdint>

typedef unsigned long long u64;
typedef unsigned int u32;

__device__ __forceinline__ u64 ffma2(u64 a, u64 b, u64 c) {
    u64 d; asm("fma.rn.f32x2 %0, %1, %2, %3;" : "=l"(d) : "l"(a), "l"(b), "l"(c)); return d;
}
__device__ __forceinline__ u64 pack2(float x, float y) {
    u64 r; asm("mov.b64 %0, {%1, %2};" : "=l"(r) : "f"(x), "f"(y)); return r;
}
__device__ __forceinline__ float2 unpack2(u64 v) {
    float2 r; asm("mov.b64 {%0, %1}, %2;" : "=f"(r.x), "=f"(r.y) : "l"(v)); return r;
}
__device__ __forceinline__ float clip1(float v) { return fminf(fmaxf(v, -1.0f), 1.0f); }
__device__ __forceinline__ u64 shflx64(u64 v, int m) {
    u32 lo = (u32)v, hi = (u32)(v >> 32);
    lo = __shfl_xor_sync(0xffffffffu, lo, m);
    hi = __shfl_xor_sync(0xffffffffu, hi, m);
    return ((u64)hi << 32) | (u64)lo;
}
__device__ __forceinline__ u64 shfl64(u64 v, int src) {
    u32 lo = (u32)v, hi = (u32)(v >> 32);
    lo = __shfl_sync(0xffffffffu, lo, src);
    hi = __shfl_sync(0xffffffffu, hi, src);
    return ((u64)hi << 32) | (u64)lo;
}
// named barrier over one group (4 warps = 128 threads)
__device__ __forceinline__ void group_bar(int id) {
    asm volatile("bar.sync %0, 128;" :: "r"(id) : "memory");
}

constexpr int NTHREADS = 512;        // 16 warps = 4 groups x 4 warps
constexpr int NGROUP   = 4;
constexpr int ROWS_G   = 16;         // rows per group (lane pair per row)
constexpr int ROWS_B   = NGROUP * ROWS_G;   // 64 rows per block-iteration
constexpr int RPW      = 4;          // rows staged per warp
constexpr int INSTRIDE = 386;        // 386 mod 32 = 2 -> conflict-free across 16 rows
constexpr int VSTRIDE  = 38;

constexpr int SW1_N = 27 * 8;
constexpr int SW2_N = 4 * 8;
constexpr int E1T_N = 19 * 16;
constexpr int E2T_N = 8 * 16;
constexpr int E3S_N = 8;
constexpr int WU_N  = SW1_N + SW2_N + E1T_N + E2T_N + E3S_N;
constexpr int IN_N  = NGROUP * ROWS_G * INSTRIDE;   // floats
constexpr int VB_N  = NGROUP * ROWS_G * VSTRIDE;    // floats
constexpr size_t SMEM_BYTES = (size_t)WU_N * 8 + (size_t)(IN_N + VB_N + 32) * 4;

__global__ __launch_bounds__(NTHREADS, 1)
void lila_kernel(const float* __restrict__ inp,
                 const float* __restrict__ W1, const float* __restrict__ b1,
                 const float* __restrict__ W2, const float* __restrict__ b2,
                 const float* __restrict__ W3, const float* __restrict__ b3,
                 const float* __restrict__ E1, const float* __restrict__ c1,
                 const float* __restrict__ E2, const float* __restrict__ c2,
                 const float* __restrict__ E3, const float* __restrict__ c3,
                 float* __restrict__ out, int B)
{
    extern __shared__ __align__(16) char smem_raw[];
    u64*   SW1 = reinterpret_cast<u64*>(smem_raw);
    u64*   SW2 = SW1 + SW1_N;
    u64*   E1T = SW2 + SW2_N;
    u64*   E2T = E1T + E1T_N;
    u64*   E3S = E2T + E2T_N;
    float* IN  = reinterpret_cast<float*>(E3S + E3S_N);
    float* VB  = IN + IN_N;
    float* c1S = VB + VB_N;       // 16
    float* c2S = c1S + 16;        // 16

    const int tid  = threadIdx.x;
    const int lane = tid & 31;
    const int warp = tid >> 5;
    const int g    = warp >> 2;          // group 0..3
    const int wsg  = warp & 3;           // warp within group 0..3
    const int r    = lane >> 1;          // row within group (0..15)
    const int h    = lane & 1;           // output half

    // ---- stage weights / constants ----
    for (int i = tid; i < SW1_N; i += NTHREADS) {
        int fp = i >> 3, o = i & 7;
        SW1[i] = pack2(W1[(2 * fp) * 8 + o], W1[(2 * fp + 1) * 8 + o]);
    }
    for (int i = tid; i < SW2_N; i += NTHREADS) {
        int fp = i >> 3, o = i & 7;
        SW2[i] = pack2(W2[(2 * fp) * 8 + o], W2[(2 * fp + 1) * 8 + o]);
    }
    for (int i = tid; i < E1T_N; i += NTHREADS) {
        int fp = i >> 4, o = i & 15;
        E1T[i] = (fp < 18) ? pack2(E1[(2 * fp) * 16 + o], E1[(2 * fp + 1) * 16 + o])
                           : pack2(E1[36 * 16 + o], 0.0f);
    }
    for (int i = tid; i < E2T_N; i += NTHREADS) {
        int fp = i >> 4, o = i & 15;
        E2T[i] = pack2(E2[(2 * fp) * 16 + o], E2[(2 * fp + 1) * 16 + o]);
    }
    if (tid < 8)  E3S[tid] = pack2(E3[2 * tid], E3[2 * tid + 1]);
    if (tid < 16) { c1S[tid] = c1[tid]; c2S[tid] = c2[tid]; }

    // ---- persistent per-lane register constants ----
    const float b10 = __ldg(b1 + 4 * h + 0), b11 = __ldg(b1 + 4 * h + 1);
    const float b12 = __ldg(b1 + 4 * h + 2), b13 = __ldg(b1 + 4 * h + 3);
    const float b20 = __ldg(b2 + 4 * h + 0), b21 = __ldg(b2 + 4 * h + 1);
    const float b22 = __ldg(b2 + 4 * h + 2), b23 = __ldg(b2 + 4 * h + 3);
    const u64 w3p0 = pack2(__ldg(W3 + 4 * h + 0), __ldg(W3 + 4 * h + 1));
    const u64 w3p1 = pack2(__ldg(W3 + 4 * h + 2), __ldg(W3 + 4 * h + 3));
    const float b3s = __ldg(b3);
    const float c3s = __ldg(c3);

    const ulonglong2* SW1v = reinterpret_cast<const ulonglong2*>(SW1);
    const ulonglong2* E1Tv = reinterpret_cast<const ulonglong2*>(E1T);
    const ulonglong2* E2Tv = reinterpret_cast<const ulonglong2*>(E2T);
    // h-shifted W2 view: w2h[f*4], w2h[f*4+1] give this lane's 4 outputs for feature-pair f
    const ulonglong2* SW2h = reinterpret_cast<const ulonglong2*>(SW2) + 2 * h;
    const int fown = 2 * h;          // own feature-pair base
    const int fpar = 2 * (1 - h);    // partner feature-pair base

    float* grp_in = IN + g * (ROWS_G * INSTRIDE);
    float* grp_vb = VB + g * (ROWS_G * VSTRIDE);
    float* lane_in = grp_in + r * INSTRIDE;
    float* lane_vb = grp_vb + r * VSTRIDE;

    // head mapping (warps 0,1 of each group handle 8 rows each)
    const int hr  = lane & 7;
    const int hoq = lane >> 3;
    const float* vrow = grp_vb + (wsg * 8 + hr) * VSTRIDE;

    const int rowsPerIter = gridDim.x * ROWS_B;
    const int barid = g + 1;
    const int rbg0 = blockIdx.x * ROWS_B + g * ROWS_G;

    __syncthreads();   // weights staged (block-wide, once)

    // ---- prologue: prefetch first iteration's rows into registers ----
    float pf[RPW][12];
    float cv[RPW];
#pragma unroll
    for (int k = 0; k < RPW; k++) {
        const int row = rbg0 + wsg * RPW + k;
        if (row < B) {
            const float* src = inp + (size_t)row * 385;
#pragma unroll
            for (int j = 0; j < 12; j++)
                pf[k][j] = __ldg(src + lane + 32 * j);
            cv[k] = (lane == 0) ? __ldg(src + 384) : 0.0f;
        } else {
#pragma unroll
            for (int j = 0; j < 12; j++) pf[k][j] = 0.0f;
            cv[k] = 0.0f;
        }
    }

    for (int rbg = rbg0; rbg < B; rbg += rowsPerIter) {

        group_bar(barid);    // protect IN vs prev compute readers, VB vs head readers

        // ---- STS: registers -> SMEM (conflict-free) ----
#pragma unroll
        for (int k = 0; k < RPW; k++) {
            const int rloc = wsg * RPW + k;
            float* dst = grp_in + rloc * INSTRIDE;
#pragma unroll
            for (int j = 0; j < 12; j++)
                dst[lane + 32 * j] = pf[k][j];
            if (lane == 0) {
                grp_vb[rloc * VSTRIDE + 36] = cv[k];
                grp_vb[rloc * VSTRIDE + 37] = 0.0f;
            }
        }
        group_bar(barid);

        // ---- prefetch NEXT iteration (overlaps the compute below) ----
        const int rbgN = rbg + rowsPerIter;
        if (rbgN < B) {
#pragma unroll
            for (int k = 0; k < RPW; k++) {
                const int row = rbgN + wsg * RPW + k;
                if (row < B) {
                    const float* src = inp + (size_t)row * 385;
#pragma unroll
                    for (int j = 0; j < 12; j++)
                        pf[k][j] = __ldg(src + lane + 32 * j);
                    cv[k] = (lane == 0) ? __ldg(src + 384) : 0.0f;
                } else {
#pragma unroll
                    for (int j = 0; j < 12; j++) pf[k][j] = 0.0f;
                    cv[k] = 0.0f;
                }
            }
        }

        // ---- compute: 12 chunks (x 0..5, yc 0/3) per group, 3 per warp ----
#pragma unroll 1
        for (int t = 0; t < 3; t++) {
            const int c   = 3 * wsg + t;     // 0..11
            const int x   = c >> 1;
            const int yc  = (c & 1) * 3;
            const float* base = lane_in + x * 48;

            u64 acc[3][4];
#pragma unroll
            for (int j = 0; j < 3; j++)
#pragma unroll
                for (int q = 0; q < 4; q++) acc[j][q] = 0ull;

            // layer 1: 27 feature-pairs x 3 patches
#pragma unroll 1
            for (int ox = 0; ox < 3; ox++) {
                const float* brow = base + ox * 48 + yc * 6;
#pragma unroll
                for (int oy = 0; oy < 3; oy++) {
#pragma unroll
                    for (int j3 = 0; j3 < 3; j3++) {
                        const int fp = 9 * ox + 3 * oy + j3;
                        const int coff = oy * 6 + 2 * j3;
                        const ulonglong2 wa = SW1v[fp * 4 + 2 * h];
                        const ulonglong2 wb = SW1v[fp * 4 + 2 * h + 1];
#pragma unroll
                        for (int j = 0; j < 3; j++) {
                            const u64 iv = *reinterpret_cast<const u64*>(brow + j * 6 + coff);
                            acc[j][0] = ffma2(iv, wa.x, acc[j][0]);
                            acc[j][1] = ffma2(iv, wa.y, acc[j][1]);
                            acc[j][2] = ffma2(iv, wb.x, acc[j][2]);
                            acc[j][3] = ffma2(iv, wb.y, acc[j][3]);
                        }
                    }
                }
            }

            // W2 weights for this lane's 4 outputs, hoisted once per chunk
            const ulonglong2 w2o0a = SW2h[(fown + 0) * 4],     w2o0b = SW2h[(fown + 0) * 4 + 1];
            const ulonglong2 w2o1a = SW2h[(fown + 1) * 4],     w2o1b = SW2h[(fown + 1) * 4 + 1];
            const ulonglong2 w2p0a = SW2h[(fpar + 0) * 4],     w2p0b = SW2h[(fpar + 0) * 4 + 1];
            const ulonglong2 w2p1a = SW2h[(fpar + 1) * 4],     w2p1b = SW2h[(fpar + 1) * 4 + 1];

            // epilogue + L2 + L3 per patch (no SELs: own pairs then partner pairs)
#pragma unroll
            for (int j = 0; j < 3; j++) {
                float2 f0 = unpack2(acc[j][0]);
                float2 f1 = unpack2(acc[j][1]);
                float2 f2 = unpack2(acc[j][2]);
                float2 f3 = unpack2(acc[j][3]);
                u64 m0 = pack2(clip1(f0.x + f0.y + b10), clip1(f1.x + f1.y + b11));
                u64 m1 = pack2(clip1(f2.x + f2.y + b12), clip1(f3.x + f3.y + b13));
                u64 p0 = shflx64(m0, 1);   // partner's first pair
                u64 p1 = shflx64(m1, 1);   // partner's second pair

                u64 a0 = 0ull, a1 = 0ull, a2 = 0ull, a3 = 0ull;
                a0 = ffma2(m0, w2o0a.x, a0); a1 = ffma2(m0, w2o0a.y, a1);
                a2 = ffma2(m0, w2o0b.x, a2); a3 = ffma2(m0, w2o0b.y, a3);
                a0 = ffma2(m1, w2o1a.x, a0); a1 = ffma2(m1, w2o1a.y, a1);
                a2 = ffma2(m1, w2o1b.x, a2); a3 = ffma2(m1, w2o1b.y, a3);
                a0 = ffma2(p0, w2p0a.x, a0); a1 = ffma2(p0, w2p0a.y, a1);
                a2 = ffma2(p0, w2p0b.x, a2); a3 = ffma2(p0, w2p0b.y, a3);
                a0 = ffma2(p1, w2p1a.x, a0); a1 = ffma2(p1, w2p1a.y, a1);
                a2 = ffma2(p1, w2p1b.x, a2); a3 = ffma2(p1, w2p1b.y, a3);

                float2 g0 = unpack2(a0), g1 = unpack2(a1);
                float2 g2 = unpack2(a2), g3 = unpack2(a3);
                u64 n0 = pack2(clip1(g0.x + g0.y + b20), clip1(g1.x + g1.y + b21));
                u64 n1 = pack2(clip1(g2.x + g2.y + b22), clip1(g3.x + g3.y + b23));

                u64 s = ffma2(n0, w3p0, ffma2(n1, w3p1, 0ull));
                float2 sf = unpack2(s);
                float part = sf.x + sf.y;
                float tot = part + __shfl_xor_sync(0xffffffffu, part, 1);
                if (h == 0) lane_vb[x * 6 + yc + j] = clip1(tot + b3s);
            }
        }
        group_bar(barid);

        // ---- head: warps 0,1 handle 8 rows each; warps 2,3 idle ----
        if (wsg < 2) {
            u64 gacc[4] = {0ull, 0ull, 0ull, 0ull};
#pragma unroll
            for (int fp = 0; fp < 19; fp++) {
                const u64 iv = *reinterpret_cast<const u64*>(vrow + 2 * fp);
                const ulonglong2 wa = E1Tv[fp * 8 + 2 * hoq];
                const ulonglong2 wb = E1Tv[fp * 8 + 2 * hoq + 1];
                gacc[0] = ffma2(iv, wa.x, gacc[0]);
                gacc[1] = ffma2(iv, wa.y, gacc[1]);
                gacc[2] = ffma2(iv, wb.x, gacc[2]);
                gacc[3] = ffma2(iv, wb.y, gacc[3]);
            }
            float gv[4];
#pragma unroll
            for (int k = 0; k < 4; k++) {
                float2 f = unpack2(gacc[k]);
                gv[k] = clip1(f.x + f.y + c1S[4 * hoq + k]);
            }
            u64 q0 = pack2(gv[0], gv[1]), q1 = pack2(gv[2], gv[3]);

            u64 z[8];
#pragma unroll
            for (int cc = 0; cc < 4; cc++) {
                z[2 * cc]     = shfl64(q0, cc * 8 + hr);
                z[2 * cc + 1] = shfl64(q1, cc * 8 + hr);
            }

            u64 d[4] = {0ull, 0ull, 0ull, 0ull};
#pragma unroll
            for (int fp = 0; fp < 8; fp++) {
                const ulonglong2 wa = E2Tv[fp * 8 + 2 * hoq];
                const ulonglong2 wb = E2Tv[fp * 8 + 2 * hoq + 1];
                d[0] = ffma2(z[fp], wa.x, d[0]);
                d[1] = ffma2(z[fp], wa.y, d[1]);
                d[2] = ffma2(z[fp], wb.x, d[2]);
                d[3] = ffma2(z[fp], wb.y, d[3]);
            }
            float dv[4];
#pragma unroll
            for (int k = 0; k < 4; k++) {
                float2 f = unpack2(d[k]);
                dv[k] = clip1(f.x + f.y + c2S[4 * hoq + k]);
            }
            u64 s = ffma2(pack2(dv[0], dv[1]), E3S[2 * hoq],
                    ffma2(pack2(dv[2], dv[3]), E3S[2 * hoq + 1], 0ull));
            float2 sf = unpack2(s);
            float part = sf.x + sf.y;
            part += __shfl_xor_sync(0xffffffffu, part, 8);
            part += __shfl_xor_sync(0xffffffffu, part, 16);
            const int row = rbg + wsg * 8 + hr;
            if (hoq == 0 && row < B) out[row] = clip1(part + c3s);
        }
    }
}

extern "C" void kernel_launch(void* const* d_in, const int* in_sizes, int n_in,
                              void* d_out, int out_size)
{
    const float* inp = (const float*)d_in[0];
    const float* W1  = (const float*)d_in[1];
    const float* b1  = (const float*)d_in[2];
    const float* W2  = (const float*)d_in[3];
    const float* b2  = (const float*)d_in[4];
    const float* W3  = (const float*)d_in[5];
    const float* b3  = (const float*)d_in[6];
    const float* E1  = (const float*)d_in[7];
    const float* c1  = (const float*)d_in[8];
    const float* E2  = (const float*)d_in[9];
    const float* c2  = (const float*)d_in[10];
    const float* E3  = (const float*)d_in[11];
    const float* c3  = (const float*)d_in[12];

    int B = in_sizes[0] / 385;

    cudaFuncSetAttribute(lila_kernel, cudaFuncAttributeMaxDynamicSharedMemorySize,
                         (int)SMEM_BYTES);

    lila_kernel<<<148, NTHREADS, SMEM_BYTES>>>(inp, W1, b1, W2, b2, W3, b3,
                                               E1, c1, E2, c2, E3, c3,
                                               (float*)d_out, B);
}

// round 12
// speedup vs baseline: 1.0388x; 1.0193x over previous
#include <cuda_runtime.h>
#include <cstdint>

typedef unsigned long long u64;
typedef unsigned int u32;

__device__ __forceinline__ u64 ffma2(u64 a, u64 b, u64 c) {
    u64 d; asm("fma.rn.f32x2 %0, %1, %2, %3;" : "=l"(d) : "l"(a), "l"(b), "l"(c)); return d;
}
__device__ __forceinline__ u64 pack2(float x, float y) {
    u64 r; asm("mov.b64 %0, {%1, %2};" : "=l"(r) : "f"(x), "f"(y)); return r;
}
__device__ __forceinline__ float2 unpack2(u64 v) {
    float2 r; asm("mov.b64 {%0, %1}, %2;" : "=f"(r.x), "=f"(r.y) : "l"(v)); return r;
}
__device__ __forceinline__ float clip1(float v) { return fminf(fmaxf(v, -1.0f), 1.0f); }
__device__ __forceinline__ u64 shflx64(u64 v, int m) {
    u32 lo = (u32)v, hi = (u32)(v >> 32);
    lo = __shfl_xor_sync(0xffffffffu, lo, m);
    hi = __shfl_xor_sync(0xffffffffu, hi, m);
    return ((u64)hi << 32) | (u64)lo;
}
__device__ __forceinline__ u64 shfl64(u64 v, int src) {
    u32 lo = (u32)v, hi = (u32)(v >> 32);
    lo = __shfl_sync(0xffffffffu, lo, src);
    hi = __shfl_sync(0xffffffffu, hi, src);
    return ((u64)hi << 32) | (u64)lo;
}
// named barrier over one group (4 warps = 128 threads)
__device__ __forceinline__ void group_bar(int id) {
    asm volatile("bar.sync %0, 128;" :: "r"(id) : "memory");
}

constexpr int NTHREADS = 512;        // 16 warps = 4 groups x 4 warps
constexpr int NGROUP   = 4;
constexpr int ROWS_G   = 16;         // rows per group (lane pair per row)
constexpr int ROWS_B   = NGROUP * ROWS_G;   // 64 rows per block-iteration
constexpr int RPW      = 4;          // rows staged per warp
constexpr int INSTRIDE = 386;        // 386 mod 32 = 2 -> conflict-free across 16 rows
constexpr int VSTRIDE  = 38;

constexpr int SW1_N = 27 * 8;
constexpr int SW2_N = 4 * 8;
constexpr int E1T_N = 19 * 16;
constexpr int E2T_N = 8 * 16;
constexpr int E3S_N = 8;
constexpr int WU_N  = SW1_N + SW2_N + E1T_N + E2T_N + E3S_N;
constexpr int IN_N  = NGROUP * ROWS_G * INSTRIDE;   // floats
constexpr int VB_N  = NGROUP * ROWS_G * VSTRIDE;    // floats
constexpr size_t SMEM_BYTES = (size_t)WU_N * 8 + (size_t)(IN_N + VB_N + 32) * 4;

__global__ __launch_bounds__(NTHREADS, 1)
void lila_kernel(const float* __restrict__ inp,
                 const float* __restrict__ W1, const float* __restrict__ b1,
                 const float* __restrict__ W2, const float* __restrict__ b2,
                 const float* __restrict__ W3, const float* __restrict__ b3,
                 const float* __restrict__ E1, const float* __restrict__ c1,
                 const float* __restrict__ E2, const float* __restrict__ c2,
                 const float* __restrict__ E3, const float* __restrict__ c3,
                 float* __restrict__ out, int B)
{
    extern __shared__ __align__(16) char smem_raw[];
    u64*   SW1 = reinterpret_cast<u64*>(smem_raw);
    u64*   SW2 = SW1 + SW1_N;
    u64*   E1T = SW2 + SW2_N;
    u64*   E2T = E1T + E1T_N;
    u64*   E3S = E2T + E2T_N;
    float* IN  = reinterpret_cast<float*>(E3S + E3S_N);
    float* VB  = IN + IN_N;
    float* c1S = VB + VB_N;       // 16
    float* c2S = c1S + 16;        // 16

    const int tid  = threadIdx.x;
    const int lane = tid & 31;
    const int warp = tid >> 5;
    const int g    = warp >> 2;          // group 0..3
    const int wsg  = warp & 3;           // warp within group 0..3
    const int r    = lane >> 1;          // row within group (0..15)
    const int h    = lane & 1;           // output half

    // ---- stage weights / constants ----
    for (int i = tid; i < SW1_N; i += NTHREADS) {
        int fp = i >> 3, o = i & 7;
        SW1[i] = pack2(W1[(2 * fp) * 8 + o], W1[(2 * fp + 1) * 8 + o]);
    }
    for (int i = tid; i < SW2_N; i += NTHREADS) {
        int fp = i >> 3, o = i & 7;
        SW2[i] = pack2(W2[(2 * fp) * 8 + o], W2[(2 * fp + 1) * 8 + o]);
    }
    for (int i = tid; i < E1T_N; i += NTHREADS) {
        int fp = i >> 4, o = i & 15;
        E1T[i] = (fp < 18) ? pack2(E1[(2 * fp) * 16 + o], E1[(2 * fp + 1) * 16 + o])
                           : pack2(E1[36 * 16 + o], 0.0f);
    }
    for (int i = tid; i < E2T_N; i += NTHREADS) {
        int fp = i >> 4, o = i & 15;
        E2T[i] = pack2(E2[(2 * fp) * 16 + o], E2[(2 * fp + 1) * 16 + o]);
    }
    if (tid < 8)  E3S[tid] = pack2(E3[2 * tid], E3[2 * tid + 1]);
    if (tid < 16) { c1S[tid] = c1[tid]; c2S[tid] = c2[tid]; }

    // ---- persistent per-lane register constants ----
    const float b10 = __ldg(b1 + 4 * h + 0), b11 = __ldg(b1 + 4 * h + 1);
    const float b12 = __ldg(b1 + 4 * h + 2), b13 = __ldg(b1 + 4 * h + 3);
    const float b20 = __ldg(b2 + 4 * h + 0), b21 = __ldg(b2 + 4 * h + 1);
    const float b22 = __ldg(b2 + 4 * h + 2), b23 = __ldg(b2 + 4 * h + 3);
    const u64 w3p0 = pack2(__ldg(W3 + 4 * h + 0), __ldg(W3 + 4 * h + 1));
    const u64 w3p1 = pack2(__ldg(W3 + 4 * h + 2), __ldg(W3 + 4 * h + 3));
    const float b3s = __ldg(b3);
    const float c3s = __ldg(c3);

    const ulonglong2* SW1v = reinterpret_cast<const ulonglong2*>(SW1);
    const ulonglong2* E1Tv = reinterpret_cast<const ulonglong2*>(E1T);
    const ulonglong2* E2Tv = reinterpret_cast<const ulonglong2*>(E2T);
    const ulonglong2* SW2h = reinterpret_cast<const ulonglong2*>(SW2) + 2 * h;
    const int fown = 2 * h;          // own feature-pair base
    const int fpar = 2 * (1 - h);    // partner feature-pair base

    float* grp_in = IN + g * (ROWS_G * INSTRIDE);
    float* grp_vb = VB + g * (ROWS_G * VSTRIDE);
    float* lane_in = grp_in + r * INSTRIDE;
    float* lane_vb = grp_vb + r * VSTRIDE;

    // head mapping (warps 0,1 of each group handle 8 rows each)
    const int hr  = lane & 7;
    const int hoq = lane >> 3;
    const float* vrow = grp_vb + (wsg * 8 + hr) * VSTRIDE;

    const int rowsPerIter = gridDim.x * ROWS_B;
    const int barid = g + 1;
    const int rbg0 = blockIdx.x * ROWS_B + g * ROWS_G;

    __syncthreads();   // weights staged (block-wide, once)

    // ---- prologue: prefetch first iteration's rows into registers ----
    float pf[RPW][12];
    float cv[RPW];
#pragma unroll
    for (int k = 0; k < RPW; k++) {
        const int row = rbg0 + wsg * RPW + k;
        if (row < B) {
            const float* src = inp + (size_t)row * 385;
#pragma unroll
            for (int j = 0; j < 12; j++)
                pf[k][j] = __ldg(src + lane + 32 * j);
            cv[k] = (lane == 0) ? __ldg(src + 384) : 0.0f;
        } else {
#pragma unroll
            for (int j = 0; j < 12; j++) pf[k][j] = 0.0f;
            cv[k] = 0.0f;
        }
    }

    for (int rbg = rbg0; rbg < B; rbg += rowsPerIter) {

        group_bar(barid);    // protect IN vs prev compute readers, VB vs head readers

        // ---- STS: registers -> SMEM (conflict-free) ----
#pragma unroll
        for (int k = 0; k < RPW; k++) {
            const int rloc = wsg * RPW + k;
            float* dst = grp_in + rloc * INSTRIDE;
#pragma unroll
            for (int j = 0; j < 12; j++)
                dst[lane + 32 * j] = pf[k][j];
            if (lane == 0) {
                grp_vb[rloc * VSTRIDE + 36] = cv[k];
                grp_vb[rloc * VSTRIDE + 37] = 0.0f;
            }
        }
        group_bar(barid);

        // ---- prefetch NEXT iteration (overlaps the compute below) ----
        const int rbgN = rbg + rowsPerIter;
        if (rbgN < B) {
#pragma unroll
            for (int k = 0; k < RPW; k++) {
                const int row = rbgN + wsg * RPW + k;
                if (row < B) {
                    const float* src = inp + (size_t)row * 385;
#pragma unroll
                    for (int j = 0; j < 12; j++)
                        pf[k][j] = __ldg(src + lane + 32 * j);
                    cv[k] = (lane == 0) ? __ldg(src + 384) : 0.0f;
                } else {
#pragma unroll
                    for (int j = 0; j < 12; j++) pf[k][j] = 0.0f;
                    cv[k] = 0.0f;
                }
            }
        }

        // ---- compute: 12 chunks (x 0..5, yc 0/3) per group, 3 per warp ----
#pragma unroll 1
        for (int t = 0; t < 3; t++) {
            const int c   = 3 * wsg + t;     // 0..11
            const int x   = c >> 1;
            const int yc  = (c & 1) * 3;
            const float* base = lane_in + x * 48;

            u64 acc[3][4];
#pragma unroll
            for (int j = 0; j < 3; j++)
#pragma unroll
                for (int q = 0; q < 4; q++) acc[j][q] = 0ull;

            // layer 1: sliding-window iv reuse — 15 loads per ox (was 27)
#pragma unroll 1
            for (int ox = 0; ox < 3; ox++) {
                const float* brow = base + ox * 48 + yc * 6;
#pragma unroll
                for (int j3 = 0; j3 < 3; j3++) {
                    // 5-column window for this j3 (cols yc..yc+4)
                    u64 iv0 = *reinterpret_cast<const u64*>(brow + 0 * 6 + 2 * j3);
                    u64 iv1 = *reinterpret_cast<const u64*>(brow + 1 * 6 + 2 * j3);
                    u64 iv2 = *reinterpret_cast<const u64*>(brow + 2 * 6 + 2 * j3);
                    u64 iv3 = *reinterpret_cast<const u64*>(brow + 3 * 6 + 2 * j3);
                    u64 iv4 = *reinterpret_cast<const u64*>(brow + 4 * 6 + 2 * j3);
#pragma unroll
                    for (int oy = 0; oy < 3; oy++) {
                        const int fp = 9 * ox + 3 * oy + j3;
                        const ulonglong2 wa = SW1v[fp * 4 + 2 * h];
                        const ulonglong2 wb = SW1v[fp * 4 + 2 * h + 1];
                        const u64 v0 = (oy == 0) ? iv0 : (oy == 1) ? iv1 : iv2;
                        const u64 v1 = (oy == 0) ? iv1 : (oy == 1) ? iv2 : iv3;
                        const u64 v2 = (oy == 0) ? iv2 : (oy == 1) ? iv3 : iv4;
                        acc[0][0] = ffma2(v0, wa.x, acc[0][0]);
                        acc[0][1] = ffma2(v0, wa.y, acc[0][1]);
                        acc[0][2] = ffma2(v0, wb.x, acc[0][2]);
                        acc[0][3] = ffma2(v0, wb.y, acc[0][3]);
                        acc[1][0] = ffma2(v1, wa.x, acc[1][0]);
                        acc[1][1] = ffma2(v1, wa.y, acc[1][1]);
                        acc[1][2] = ffma2(v1, wb.x, acc[1][2]);
                        acc[1][3] = ffma2(v1, wb.y, acc[1][3]);
                        acc[2][0] = ffma2(v2, wa.x, acc[2][0]);
                        acc[2][1] = ffma2(v2, wa.y, acc[2][1]);
                        acc[2][2] = ffma2(v2, wb.x, acc[2][2]);
                        acc[2][3] = ffma2(v2, wb.y, acc[2][3]);
                    }
                }
            }

            // W2 weights for this lane's 4 outputs, hoisted once per chunk
            const ulonglong2 w2o0a = SW2h[(fown + 0) * 4],     w2o0b = SW2h[(fown + 0) * 4 + 1];
            const ulonglong2 w2o1a = SW2h[(fown + 1) * 4],     w2o1b = SW2h[(fown + 1) * 4 + 1];
            const ulonglong2 w2p0a = SW2h[(fpar + 0) * 4],     w2p0b = SW2h[(fpar + 0) * 4 + 1];
            const ulonglong2 w2p1a = SW2h[(fpar + 1) * 4],     w2p1b = SW2h[(fpar + 1) * 4 + 1];

            // epilogue + L2 + L3 per patch (no SELs: own pairs then partner pairs)
#pragma unroll
            for (int j = 0; j < 3; j++) {
                float2 f0 = unpack2(acc[j][0]);
                float2 f1 = unpack2(acc[j][1]);
                float2 f2 = unpack2(acc[j][2]);
                float2 f3 = unpack2(acc[j][3]);
                u64 m0 = pack2(clip1(f0.x + f0.y + b10), clip1(f1.x + f1.y + b11));
                u64 m1 = pack2(clip1(f2.x + f2.y + b12), clip1(f3.x + f3.y + b13));
                u64 p0 = shflx64(m0, 1);   // partner's first pair
                u64 p1 = shflx64(m1, 1);   // partner's second pair

                u64 a0 = 0ull, a1 = 0ull, a2 = 0ull, a3 = 0ull;
                a0 = ffma2(m0, w2o0a.x, a0); a1 = ffma2(m0, w2o0a.y, a1);
                a2 = ffma2(m0, w2o0b.x, a2); a3 = ffma2(m0, w2o0b.y, a3);
                a0 = ffma2(m1, w2o1a.x, a0); a1 = ffma2(m1, w2o1a.y, a1);
                a2 = ffma2(m1, w2o1b.x, a2); a3 = ffma2(m1, w2o1b.y, a3);
                a0 = ffma2(p0, w2p0a.x, a0); a1 = ffma2(p0, w2p0a.y, a1);
                a2 = ffma2(p0, w2p0b.x, a2); a3 = ffma2(p0, w2p0b.y, a3);
                a0 = ffma2(p1, w2p1a.x, a0); a1 = ffma2(p1, w2p1a.y, a1);
                a2 = ffma2(p1, w2p1b.x, a2); a3 = ffma2(p1, w2p1b.y, a3);

                float2 g0 = unpack2(a0), g1 = unpack2(a1);
                float2 g2 = unpack2(a2), g3 = unpack2(a3);
                u64 n0 = pack2(clip1(g0.x + g0.y + b20), clip1(g1.x + g1.y + b21));
                u64 n1 = pack2(clip1(g2.x + g2.y + b22), clip1(g3.x + g3.y + b23));

                u64 s = ffma2(n0, w3p0, ffma2(n1, w3p1, 0ull));
                float2 sf = unpack2(s);
                float part = sf.x + sf.y;
                float tot = part + __shfl_xor_sync(0xffffffffu, part, 1);
                if (h == 0) lane_vb[x * 6 + yc + j] = clip1(tot + b3s);
            }
        }
        group_bar(barid);

        // ---- head: warps 0,1 handle 8 rows each; warps 2,3 idle ----
        if (wsg < 2) {
            u64 gacc[4] = {0ull, 0ull, 0ull, 0ull};
#pragma unroll
            for (int fp = 0; fp < 19; fp++) {
                const u64 iv = *reinterpret_cast<const u64*>(vrow + 2 * fp);
                const ulonglong2 wa = E1Tv[fp * 8 + 2 * hoq];
                const ulonglong2 wb = E1Tv[fp * 8 + 2 * hoq + 1];
                gacc[0] = ffma2(iv, wa.x, gacc[0]);
                gacc[1] = ffma2(iv, wa.y, gacc[1]);
                gacc[2] = ffma2(iv, wb.x, gacc[2]);
                gacc[3] = ffma2(iv, wb.y, gacc[3]);
            }
            float gv[4];
#pragma unroll
            for (int k = 0; k < 4; k++) {
                float2 f = unpack2(gacc[k]);
                gv[k] = clip1(f.x + f.y + c1S[4 * hoq + k]);
            }
            u64 q0 = pack2(gv[0], gv[1]), q1 = pack2(gv[2], gv[3]);

            u64 z[8];
#pragma unroll
            for (int cc = 0; cc < 4; cc++) {
                z[2 * cc]     = shfl64(q0, cc * 8 + hr);
                z[2 * cc + 1] = shfl64(q1, cc * 8 + hr);
            }

            u64 d[4] = {0ull, 0ull, 0ull, 0ull};
#pragma unroll
            for (int fp = 0; fp < 8; fp++) {
                const ulonglong2 wa = E2Tv[fp * 8 + 2 * hoq];
                const ulonglong2 wb = E2Tv[fp * 8 + 2 * hoq + 1];
                d[0] = ffma2(z[fp], wa.x, d[0]);
                d[1] = ffma2(z[fp], wa.y, d[1]);
                d[2] = ffma2(z[fp], wb.x, d[2]);
                d[3] = ffma2(z[fp], wb.y, d[3]);
            }
            float dv[4];
#pragma unroll
            for (int k = 0; k < 4; k++) {
                float2 f = unpack2(d[k]);
                dv[k] = clip1(f.x + f.y + c2S[4 * hoq + k]);
            }
            u64 s = ffma2(pack2(dv[0], dv[1]), E3S[2 * hoq],
                    ffma2(pack2(dv[2], dv[3]), E3S[2 * hoq + 1], 0ull));
            float2 sf = unpack2(s);
            float part = sf.x + sf.y;
            part += __shfl_xor_sync(0xffffffffu, part, 8);
            part += __shfl_xor_sync(0xffffffffu, part, 16);
            const int row = rbg + wsg * 8 + hr;
            if (hoq == 0 && row < B) out[row] = clip1(part + c3s);
        }
    }
}

extern "C" void kernel_launch(void* const* d_in, const int* in_sizes, int n_in,
                              void* d_out, int out_size)
{
    const float* inp = (const float*)d_in[0];
    const float* W1  = (const float*)d_in[1];
    const float* b1  = (const float*)d_in[2];
    const float* W2  = (const float*)d_in[3];
    const float* b2  = (const float*)d_in[4];
    const float* W3  = (const float*)d_in[5];
    const float* b3  = (const float*)d_in[6];
    const float* E1  = (const float*)d_in[7];
    const float* c1  = (const float*)d_in[8];
    const float* E2  = (const float*)d_in[9];
    const float* c2  = (const float*)d_in[10];
    const float* E3  = (const float*)d_in[11];
    const float* c3  = (const float*)d_in[12];

    int B = in_sizes[0] / 385;

    cudaFuncSetAttribute(lila_kernel, cudaFuncAttributeMaxDynamicSharedMemorySize,
                         (int)SMEM_BYTES);

    lila_kernel<<<148, NTHREADS, SMEM_BYTES>>>(inp, W1, b1, W2, b2, W3, b3,
                                               E1, c1, E2, c2, E3, c3,
                                               (float*)d_out, B);
}